// round 1
// baseline (speedup 1.0000x reference)
#include <cuda_runtime.h>
#include <cuda_bf16.h>

// CRF NLL: B=1024 sequences, T=2048 timesteps, K=9 tags (START=7, STOP=8).
// Effective state space is 7 (tags 0..6) because exp(-10000) == 0.0f exactly.
//
// Pipeline:
//   prep:    E[j][i] = exp(trans[j][i]) for j,i in 0..6   (device global)
//   chunk:   per (seq, chunk of 128 steps): 7x7 propagation matrix in
//            linear domain with periodic power-of-2 renorm; columns mapped
//            to lanes (7 active lanes / 8-lane group, 4 groups per warp,
//            consecutive chunks of the same sequence per warp).
//   combine: per seq: v = step0 vector; fold 16 chunk matrices (log-domain
//            lse mat-vec); fwd[b] = lse_j(v[j] + trans[STOP][j]).
//   gold:    per seq block: sum_t trans[tag_t][prev] + feat[t][tag_t]
//            (+ trans[STOP][last]); fixed-order tree reduction.
//   final:   out[0] = mean(fwd - gold), fixed-order tree reduction.

#define BB 1024
#define TT 2048
#define KK 9
#define CH 16
#define CL 128   // chunk length; chunks cover t in [1, 2048)

__device__ float g_E[49];
__device__ float g_logM[(size_t)BB * CH * 49];
__device__ float g_fwd[BB];
__device__ float g_gold[BB];

__global__ void prep_kernel(const float* __restrict__ trans) {
    int i = threadIdx.x;
    if (i < 49) {
        int j = i / 7, ii = i % 7;
        g_E[i] = __expf(trans[j * KK + ii]);
    }
}

__global__ __launch_bounds__(128) void chunk_kernel(
    const float* __restrict__ feats,
    const int* __restrict__ lengths)
{
    int w    = (blockIdx.x * blockDim.x + threadIdx.x) >> 5;  // global warp id
    int lane = threadIdx.x & 31;
    int b  = w >> 2;        // sequence
    int sb = w & 3;         // superblock of 4 consecutive chunks
    int g  = lane >> 3;     // group within warp (chunk)
    int c  = lane & 7;      // column of the 7x7 matrix (c==7 idle)

    int k  = sb * 4 + g;            // chunk index 0..15
    int t0 = 1 + k * CL;            // first timestep of chunk
    int t1 = min(t0 + CL, TT);      // end of chunk window
    int len = lengths[b];
    int trips = min(t1, len) - t0;  if (trips < 0) trips = 0;

    // warp-uniform loop bound = trips of group 0 (largest within warp)
    int t00 = 1 + sb * 4 * CL;
    int nsteps = min(min(t00 + CL, TT), len) - t00;  if (nsteps < 0) nsteps = 0;

    float E[7][7];
#pragma unroll
    for (int j = 0; j < 7; j++)
#pragma unroll
        for (int i = 0; i < 7; i++)
            E[j][i] = g_E[j * 7 + i];

    float p[7];
#pragma unroll
    for (int j = 0; j < 7; j++) p[j] = (j == c) ? 1.0f : 0.0f;
    float m = 0.0f;   // accumulated log-scale (nats)

    const float* fb = feats + (size_t)b * TT * KK;
    float f[7];
    if (trips > 0) {
        const float* fr = fb + (size_t)t0 * KK;
#pragma unroll
        for (int j = 0; j < 7; j++) f[j] = fr[j];
    }

    for (int s = 0; s < nsteps; s++) {
        if (s < trips) {
            float ef[7];
#pragma unroll
            for (int j = 0; j < 7; j++) ef[j] = __expf(f[j]);
            // prefetch next row while the FMA block runs
            if (s + 1 < trips) {
                const float* fr = fb + (size_t)(t0 + s + 1) * KK;
#pragma unroll
                for (int j = 0; j < 7; j++) f[j] = fr[j];
            }
            float pn[7];
#pragma unroll
            for (int j = 0; j < 7; j++) {
                float a = E[j][0] * p[0];
#pragma unroll
                for (int i = 1; i < 7; i++) a = fmaf(E[j][i], p[i], a);
                pn[j] = a * ef[j];
            }
#pragma unroll
            for (int j = 0; j < 7; j++) p[j] = pn[j];

            if ((s & 3) == 3) {   // renorm by power of 2 every 4 steps
                float pm = p[0];
#pragma unroll
                for (int j = 1; j < 7; j++) pm = fmaxf(pm, p[j]);
                int e = (int)((__float_as_uint(pm) >> 23) & 255) - 127;
                float scale = __uint_as_float((unsigned)(127 - e) << 23);
#pragma unroll
                for (int j = 0; j < 7; j++) p[j] *= scale;
                m += (float)e * 0.69314718055994531f;
            }
        }
    }

    if (c < 7) {
        float* out = g_logM + ((size_t)b * CH + k) * 49;
#pragma unroll
        for (int j = 0; j < 7; j++)
            out[j * 7 + c] = __logf(fmaxf(p[j], 1e-35f)) + m;
    }
}

__global__ void combine_kernel(const float* __restrict__ feats,
                               const float* __restrict__ trans)
{
    int b = blockIdx.x * blockDim.x + threadIdx.x;
    if (b >= BB) return;

    float v[7];
    const float* f0 = feats + (size_t)b * TT * KK;   // t = 0 row
#pragma unroll
    for (int j = 0; j < 7; j++) v[j] = trans[j * KK + 7] + f0[j];

    const float* Mb = g_logM + (size_t)b * CH * 49;
    for (int k = 0; k < CH; k++) {
        const float* Mk = Mb + k * 49;
        float w[7];
#pragma unroll
        for (int j = 0; j < 7; j++) {
            float a[7];
            float mx = Mk[j * 7 + 0] + v[0];
            a[0] = mx;
#pragma unroll
            for (int i = 1; i < 7; i++) {
                a[i] = Mk[j * 7 + i] + v[i];
                mx = fmaxf(mx, a[i]);
            }
            float s = 0.0f;
#pragma unroll
            for (int i = 0; i < 7; i++) s += __expf(a[i] - mx);
            w[j] = mx + __logf(s);
        }
#pragma unroll
        for (int j = 0; j < 7; j++) v[j] = w[j];
    }

    // final: lse_j(v[j] + trans[STOP][j]), j in 0..6
    float a[7];
    float mx = v[0] + trans[8 * KK + 0];
    a[0] = mx;
#pragma unroll
    for (int j = 1; j < 7; j++) {
        a[j] = v[j] + trans[8 * KK + j];
        mx = fmaxf(mx, a[j]);
    }
    float s = 0.0f;
#pragma unroll
    for (int j = 0; j < 7; j++) s += __expf(a[j] - mx);
    g_fwd[b] = mx + __logf(s);
}

__global__ void gold_kernel(const float* __restrict__ feats,
                            const float* __restrict__ trans,
                            const int* __restrict__ tags,
                            const int* __restrict__ lengths)
{
    int b = blockIdx.x;
    int len = lengths[b];
    const int*   tg = tags  + (size_t)b * TT;
    const float* fb = feats + (size_t)b * TT * KK;

    float acc = 0.0f;
    for (int t = threadIdx.x; t < len; t += blockDim.x) {
        int cur  = tg[t];
        int prev = (t == 0) ? 7 : tg[t - 1];
        acc += trans[cur * KK + prev] + fb[t * KK + cur];
    }

    __shared__ float sm[256];
    sm[threadIdx.x] = acc;
    __syncthreads();
    for (int o = 128; o > 0; o >>= 1) {
        if (threadIdx.x < o) sm[threadIdx.x] += sm[threadIdx.x + o];
        __syncthreads();
    }
    if (threadIdx.x == 0)
        g_gold[b] = sm[0] + trans[8 * KK + tg[len - 1]];
}

__global__ void final_kernel(float* __restrict__ out)
{
    __shared__ float sm[256];
    float a = 0.0f;
    for (int i = threadIdx.x; i < BB; i += 256)
        a += g_fwd[i] - g_gold[i];
    sm[threadIdx.x] = a;
    __syncthreads();
    for (int o = 128; o > 0; o >>= 1) {
        if (threadIdx.x < o) sm[threadIdx.x] += sm[threadIdx.x + o];
        __syncthreads();
    }
    if (threadIdx.x == 0) out[0] = sm[0] / (float)BB;
}

extern "C" void kernel_launch(void* const* d_in, const int* in_sizes, int n_in,
                              void* d_out, int out_size)
{
    const float* feats   = (const float*)d_in[0];
    const float* trans   = (const float*)d_in[1];
    const int*   tags    = (const int*)d_in[2];
    const int*   lengths = (const int*)d_in[3];
    float* out = (float*)d_out;

    prep_kernel<<<1, 64>>>(trans);
    // B*4 warps total, 128 threads (4 warps) per block -> 1024 blocks
    chunk_kernel<<<(BB * 4 * 32) / 128, 128>>>(feats, lengths);
    gold_kernel<<<BB, 256>>>(feats, trans, tags, lengths);
    combine_kernel<<<BB / 256, 256>>>(feats, trans);
    final_kernel<<<1, 256>>>(out);
}

// round 2
// speedup vs baseline: 1.2686x; 1.2686x over previous
#include <cuda_runtime.h>
#include <cuda_bf16.h>

// CRF NLL: B=1024, T=2048, K=9 (START=7, STOP=8). Effective states = 7
// because exp(-10000) == 0.0f exactly.
//
// chunk:   32 chunks of 64 steps per sequence; each 8-lane group of a warp
//          computes one chunk's 7x7 propagation matrix in linear domain
//          (columns -> lanes), f32x2-packed FFMA2 mainloop, power-of-2
//          renorm every 4 steps. 8 warps per sequence (4 consecutive
//          chunks per warp).
// combine: one warp per sequence; lanes 0..6 own rows; fold 32 log-domain
//          matrices with shfl-broadcast lse mat-vec.
// gold:    per-seq block gather + fixed-order tree reduction.
// final:   deterministic mean of (fwd - gold).

#define BB 1024
#define TT 2048
#define KK 9
#define CH 32
#define CL 64

typedef unsigned long long u64;

__device__ float g_E[49];
__device__ float g_logM[(size_t)BB * CH * 49];
__device__ float g_fwd[BB];
__device__ float g_gold[BB];

__device__ __forceinline__ u64 pk2(float lo, float hi) {
    u64 r; asm("mov.b64 %0, {%1,%2};" : "=l"(r) : "f"(lo), "f"(hi)); return r;
}
__device__ __forceinline__ void upk2(float& lo, float& hi, u64 v) {
    asm("mov.b64 {%0,%1}, %2;" : "=f"(lo), "=f"(hi) : "l"(v));
}
__device__ __forceinline__ u64 fma2(u64 a, u64 b, u64 c) {
    u64 r; asm("fma.rn.f32x2 %0, %1, %2, %3;" : "=l"(r) : "l"(a), "l"(b), "l"(c)); return r;
}
__device__ __forceinline__ u64 mul2(u64 a, u64 b) {
    u64 r; asm("mul.rn.f32x2 %0, %1, %2;" : "=l"(r) : "l"(a), "l"(b)); return r;
}

__global__ void prep_kernel(const float* __restrict__ trans) {
    int i = threadIdx.x;
    if (i < 49) {
        int j = i / 7, ii = i % 7;
        g_E[i] = __expf(trans[j * KK + ii]);
    }
}

__global__ __launch_bounds__(128) void chunk_kernel(
    const float* __restrict__ feats,
    const int* __restrict__ lengths)
{
    int w    = (blockIdx.x * blockDim.x + threadIdx.x) >> 5;
    int lane = threadIdx.x & 31;
    int b  = w >> 3;        // sequence (8 warps per seq)
    int sb = w & 7;         // superblock of 4 consecutive chunks
    int g  = lane >> 3;     // group within warp (chunk)
    int c  = lane & 7;      // matrix column (c==7 idle)

    int k  = sb * 4 + g;            // chunk 0..31
    int t0 = 1 + k * CL;
    int len = lengths[b];
    int trips = min(min(t0 + CL, TT), len) - t0;  if (trips < 0) trips = 0;

    // warp-uniform loop bound = group 0's trips (largest within warp)
    int t00 = 1 + sb * 4 * CL;
    int nsteps = min(min(t00 + CL, TT), len) - t00;  if (nsteps < 0) nsteps = 0;

    // E packed along j: E2[jp][i] = (E[2jp][i], E[2jp+1][i]); jp==3 hi = 0
    u64 E2[4][7];
#pragma unroll
    for (int jp = 0; jp < 4; jp++)
#pragma unroll
        for (int i = 0; i < 7; i++)
            E2[jp][i] = pk2(g_E[(2 * jp) * 7 + i],
                            (jp < 3) ? g_E[(2 * jp + 1) * 7 + i] : 0.0f);

    // p packed: (p0,p1)(p2,p3)(p4,p5)(p6,0); init = unit vector at column c
    u64 P[4];
#pragma unroll
    for (int jp = 0; jp < 4; jp++)
        P[jp] = pk2((c == 2 * jp) ? 1.0f : 0.0f,
                    (jp < 3 && c == 2 * jp + 1) ? 1.0f : 0.0f);
    float m = 0.0f;

    const float* fb = feats + (size_t)b * TT * KK;
    float f[7];
    if (trips > 0) {
        const float* fr = fb + (size_t)t0 * KK;
#pragma unroll
        for (int j = 0; j < 7; j++) f[j] = fr[j];
    }

    for (int s = 0; s < nsteps; s++) {
        if (s < trips) {
            float ef[7];
#pragma unroll
            for (int j = 0; j < 7; j++) ef[j] = __expf(f[j]);
            if (s + 1 < trips) {
                const float* fr = fb + (size_t)(t0 + s + 1) * KK;
#pragma unroll
                for (int j = 0; j < 7; j++) f[j] = fr[j];
            }
            // unpack p, build broadcast packs
            float ps[8];
#pragma unroll
            for (int jp = 0; jp < 4; jp++) upk2(ps[2 * jp], ps[2 * jp + 1], P[jp]);
            u64 pp[7];
#pragma unroll
            for (int i = 0; i < 7; i++) pp[i] = pk2(ps[i], ps[i]);
            // matvec: acc[jp] = sum_i E2[jp][i] * p[i]
            u64 acc[4];
#pragma unroll
            for (int jp = 0; jp < 4; jp++) {
                u64 a = mul2(E2[jp][0], pp[0]);
#pragma unroll
                for (int i = 1; i < 7; i++) a = fma2(E2[jp][i], pp[i], a);
                acc[jp] = a;
            }
            u64 efp[4];
            efp[0] = pk2(ef[0], ef[1]);
            efp[1] = pk2(ef[2], ef[3]);
            efp[2] = pk2(ef[4], ef[5]);
            efp[3] = pk2(ef[6], 0.0f);
#pragma unroll
            for (int jp = 0; jp < 4; jp++) P[jp] = mul2(acc[jp], efp[jp]);

            if ((s & 3) == 3) {   // power-of-2 renorm
                float q[8];
#pragma unroll
                for (int jp = 0; jp < 4; jp++) upk2(q[2 * jp], q[2 * jp + 1], P[jp]);
                float pm = q[0];
#pragma unroll
                for (int j = 1; j < 7; j++) pm = fmaxf(pm, q[j]);
                int e = (int)((__float_as_uint(pm) >> 23) & 255) - 127;
                u64 sc = pk2(__uint_as_float((unsigned)(127 - e) << 23),
                             __uint_as_float((unsigned)(127 - e) << 23));
#pragma unroll
                for (int jp = 0; jp < 4; jp++) P[jp] = mul2(P[jp], sc);
                m += (float)e * 0.69314718055994531f;
            }
        }
    }

    if (c < 7) {
        float q[8];
#pragma unroll
        for (int jp = 0; jp < 4; jp++) upk2(q[2 * jp], q[2 * jp + 1], P[jp]);
        float* out = g_logM + ((size_t)b * CH + k) * 49;
#pragma unroll
        for (int j = 0; j < 7; j++)
            out[j * 7 + c] = __logf(fmaxf(q[j], 1e-35f)) + m;
    }
}

// one warp per sequence; lanes 0..6 own rows of the lse mat-vec fold
__global__ __launch_bounds__(256) void combine_kernel(
    const float* __restrict__ feats,
    const float* __restrict__ trans)
{
    int w    = (blockIdx.x * blockDim.x + threadIdx.x) >> 5;
    int lane = threadIdx.x & 31;
    if (w >= BB) return;
    int b = w;
    int j = lane;
    bool act = (lane < 7);

    float v = -10000.0f;
    if (act)
        v = trans[j * KK + 7] + feats[(size_t)b * TT * KK + j];

    const float* Mb = g_logM + (size_t)b * CH * 49;
    for (int k = 0; k < CH; k++) {
        const float* Mk = Mb + k * 49;
        float vv[7];
#pragma unroll
        for (int i = 0; i < 7; i++) vv[i] = __shfl_sync(0xffffffffu, v, i);
        if (act) {
            float a[7];
            float mx = Mk[j * 7 + 0] + vv[0];
            a[0] = mx;
#pragma unroll
            for (int i = 1; i < 7; i++) {
                a[i] = Mk[j * 7 + i] + vv[i];
                mx = fmaxf(mx, a[i]);
            }
            float s = 0.0f;
#pragma unroll
            for (int i = 0; i < 7; i++) s += __expf(a[i] - mx);
            v = mx + __logf(s);
        }
    }

    // fwd[b] = lse_j(v[j] + trans[STOP][j]) via 8-lane butterfly
    float r = act ? (v + trans[8 * KK + j]) : -10000.0f;
    float mx = r;
#pragma unroll
    for (int o = 4; o > 0; o >>= 1)
        mx = fmaxf(mx, __shfl_xor_sync(0xffffffffu, mx, o));
    float e = __expf(r - mx);
#pragma unroll
    for (int o = 4; o > 0; o >>= 1)
        e += __shfl_xor_sync(0xffffffffu, e, o);
    if (lane == 0) g_fwd[b] = mx + __logf(e);
}

__global__ void gold_kernel(const float* __restrict__ feats,
                            const float* __restrict__ trans,
                            const int* __restrict__ tags,
                            const int* __restrict__ lengths)
{
    int b = blockIdx.x;
    int len = lengths[b];
    const int*   tg = tags  + (size_t)b * TT;
    const float* fb = feats + (size_t)b * TT * KK;

    float acc = 0.0f;
    for (int t = threadIdx.x; t < len; t += blockDim.x) {
        int cur  = tg[t];
        int prev = (t == 0) ? 7 : tg[t - 1];
        acc += trans[cur * KK + prev] + fb[t * KK + cur];
    }

    __shared__ float sm[256];
    sm[threadIdx.x] = acc;
    __syncthreads();
    for (int o = 128; o > 0; o >>= 1) {
        if (threadIdx.x < o) sm[threadIdx.x] += sm[threadIdx.x + o];
        __syncthreads();
    }
    if (threadIdx.x == 0)
        g_gold[b] = sm[0] + trans[8 * KK + tg[len - 1]];
}

__global__ void final_kernel(float* __restrict__ out)
{
    __shared__ float sm[256];
    float a = 0.0f;
    for (int i = threadIdx.x; i < BB; i += 256)
        a += g_fwd[i] - g_gold[i];
    sm[threadIdx.x] = a;
    __syncthreads();
    for (int o = 128; o > 0; o >>= 1) {
        if (threadIdx.x < o) sm[threadIdx.x] += sm[threadIdx.x + o];
        __syncthreads();
    }
    if (threadIdx.x == 0) out[0] = sm[0] / (float)BB;
}

extern "C" void kernel_launch(void* const* d_in, const int* in_sizes, int n_in,
                              void* d_out, int out_size)
{
    const float* feats   = (const float*)d_in[0];
    const float* trans   = (const float*)d_in[1];
    const int*   tags    = (const int*)d_in[2];
    const int*   lengths = (const int*)d_in[3];
    float* out = (float*)d_out;

    prep_kernel<<<1, 64>>>(trans);
    // BB*8 warps, 128 threads per block -> 2048 blocks
    chunk_kernel<<<(BB * 8 * 32) / 128, 128>>>(feats, lengths);
    gold_kernel<<<BB, 256>>>(feats, trans, tags, lengths);
    // BB warps, 256 threads per block -> BB/8 blocks
    combine_kernel<<<BB / 8, 256>>>(feats, trans);
    final_kernel<<<1, 256>>>(out);
}

// round 6
// speedup vs baseline: 2.1251x; 1.6751x over previous
#include <cuda_runtime.h>
#include <cuda_bf16.h>

// CRF NLL: B=1024, T=2048, K=9 (START=7, STOP=8). Effective states = 7
// (exp(-10000) == 0.0f exactly).
//
// chunk:   64 chunks of 32 steps/seq. Each 8-lane group propagates one
//          chunk's 7x7 matrix in linear domain (columns->lanes), f32x2
//          FFMA2 matvec, cooperative feat loads (1 LDG/step) + 1 MUFU exp
//          + width-8 shfl broadcast, power-of-2 renorm every 4 steps.
//          Lane 7 of each group accumulates the gold path score for the
//          same timesteps. Output: linear 7x7 matrix (rows padded to 8)
//          + int pow2 scale + gold partial.
// combine: 4 seqs/warp; lanes 0..6 = rows. 64 linear folds (7 FFMA each,
//          no MUFU), LDG.128 rows prefetched 2 deep, int renorm every 4
//          folds. Adds step-0 and STOP gold terms; writes fwd - gold.
// final:   deterministic mean.

#define BB 1024
#define TT 2048
#define KK 9
#define CH 64
#define CL 32
#define LN2 0.69314718055994531f

typedef unsigned long long u64;

__device__ float g_E[49];
__device__ float g_M[(size_t)BB * CH * 64];   // 16.8 MB, rows padded to 8
__device__ int   g_Msc[BB * CH];
__device__ float g_goldP[BB * CH];
__device__ float g_diff[BB];

__device__ __forceinline__ u64 pk2(float lo, float hi) {
    u64 r; asm("mov.b64 %0, {%1,%2};" : "=l"(r) : "f"(lo), "f"(hi)); return r;
}
__device__ __forceinline__ void upk2(float& lo, float& hi, u64 v) {
    asm("mov.b64 {%0,%1}, %2;" : "=f"(lo), "=f"(hi) : "l"(v));
}
__device__ __forceinline__ u64 fma2(u64 a, u64 b, u64 c) {
    u64 r; asm("fma.rn.f32x2 %0, %1, %2, %3;" : "=l"(r) : "l"(a), "l"(b), "l"(c)); return r;
}
__device__ __forceinline__ u64 mul2(u64 a, u64 b) {
    u64 r; asm("mul.rn.f32x2 %0, %1, %2;" : "=l"(r) : "l"(a), "l"(b)); return r;
}
__device__ __forceinline__ int fexp(float x) {
    return (int)((__float_as_uint(x) >> 23) & 255) - 127;
}
__device__ __forceinline__ float p2f(int e) {   // 2^e, flush if too small
    return (e < -126) ? 0.0f : __uint_as_float((unsigned)(e + 127) << 23);
}

__global__ void prep_kernel(const float* __restrict__ trans) {
    int i = threadIdx.x;
    if (i < 49) g_E[i] = __expf(trans[(i / 7) * KK + (i % 7)]);
}

__global__ __launch_bounds__(128) void chunk_kernel(
    const float* __restrict__ feats, const float* __restrict__ trans,
    const int* __restrict__ tags, const int* __restrict__ lengths)
{
    int w    = (blockIdx.x * 128 + threadIdx.x) >> 5;
    int lane = threadIdx.x & 31;
    int b  = w >> 4;        // 16 warps per sequence
    int sb = w & 15;
    int g  = lane >> 3;     // group (chunk) within warp
    int c  = lane & 7;      // matrix column; c==7 handles gold

    int k  = sb * 4 + g;
    int t0 = 1 + k * CL;
    int len = lengths[b];
    int trips = min(min(t0 + CL, TT), len) - t0;  if (trips < 0) trips = 0;
    int t00 = 1 + sb * 4 * CL;
    int nsteps = min(min(t00 + CL, TT), len) - t00;  if (nsteps < 0) nsteps = 0;

    u64 E2[4][7];
#pragma unroll
    for (int jp = 0; jp < 4; jp++)
#pragma unroll
        for (int i = 0; i < 7; i++)
            E2[jp][i] = pk2(g_E[(2 * jp) * 7 + i],
                            (jp < 3) ? g_E[(2 * jp + 1) * 7 + i] : 0.0f);

    u64 P[4];
#pragma unroll
    for (int jp = 0; jp < 4; jp++)
        P[jp] = pk2((c == 2 * jp) ? 1.0f : 0.0f,
                    (jp < 3 && c == 2 * jp + 1) ? 1.0f : 0.0f);
    int m = 0;

    const float* fb = feats + (size_t)b * TT * KK;
    const int*   tb = tags  + (size_t)b * TT;

    float f_cur = 0.0f;
    int tag_cur = 0, tag_prev = 0;
    if (nsteps > 0) {
        if (c < 7) f_cur = fb[t0 * KK + c];
        else { tag_cur = tb[t0]; tag_prev = tb[t0 - 1]; }
    }
    float gacc = 0.0f;

    for (int s = 0; s < nsteps; s++) {
        // prefetch next step (clamped)
        int tn = min(t0 + s + 1, TT - 1);
        float f_nxt = 0.0f; int tag_nxt = 0;
        if (c < 7) f_nxt = fb[tn * KK + c];
        else       tag_nxt = tb[tn];

        float efs = __expf(f_cur);                       // 1 MUFU for whole warp
        float ef0 = __shfl_sync(0xffffffffu, efs, 0, 8);
        float ef1 = __shfl_sync(0xffffffffu, efs, 1, 8);
        float ef2 = __shfl_sync(0xffffffffu, efs, 2, 8);
        float ef3 = __shfl_sync(0xffffffffu, efs, 3, 8);
        float ef4 = __shfl_sync(0xffffffffu, efs, 4, 8);
        float ef5 = __shfl_sync(0xffffffffu, efs, 5, 8);
        float ef6 = __shfl_sync(0xffffffffu, efs, 6, 8);
        float ftag = __shfl_sync(0xffffffffu, f_cur, tag_cur, 8);

        bool act = (s < trips);
        if (c == 7 && act)
            gacc += trans[tag_cur * KK + tag_prev] + ftag;

        if (act) {
            float ps0, ps1, ps2, ps3, ps4, ps5, ps6, ps7;
            upk2(ps0, ps1, P[0]); upk2(ps2, ps3, P[1]);
            upk2(ps4, ps5, P[2]); upk2(ps6, ps7, P[3]);
            u64 pp[7];
            pp[0] = pk2(ps0, ps0); pp[1] = pk2(ps1, ps1); pp[2] = pk2(ps2, ps2);
            pp[3] = pk2(ps3, ps3); pp[4] = pk2(ps4, ps4); pp[5] = pk2(ps5, ps5);
            pp[6] = pk2(ps6, ps6);
            u64 acc[4];
#pragma unroll
            for (int jp = 0; jp < 4; jp++) {
                u64 a = mul2(E2[jp][0], pp[0]);
#pragma unroll
                for (int i = 1; i < 7; i++) a = fma2(E2[jp][i], pp[i], a);
                acc[jp] = a;
            }
            u64 efp0 = pk2(ef0, ef1), efp1 = pk2(ef2, ef3);
            u64 efp2 = pk2(ef4, ef5), efp3 = pk2(ef6, 0.0f);
            P[0] = mul2(acc[0], efp0); P[1] = mul2(acc[1], efp1);
            P[2] = mul2(acc[2], efp2); P[3] = mul2(acc[3], efp3);

            if ((s & 3) == 3) {
                float q0, q1, q2, q3, q4, q5, q6, q7;
                upk2(q0, q1, P[0]); upk2(q2, q3, P[1]);
                upk2(q4, q5, P[2]); upk2(q6, q7, P[3]);
                float pm = fmaxf(fmaxf(fmaxf(q0, q1), fmaxf(q2, q3)),
                                 fmaxf(fmaxf(q4, q5), q6));
                int e = fexp(pm);
                float s1 = p2f(-e);
                u64 sc = pk2(s1, s1);
                P[0] = mul2(P[0], sc); P[1] = mul2(P[1], sc);
                P[2] = mul2(P[2], sc); P[3] = mul2(P[3], sc);
                m += e;
            }
        }
        f_cur = f_nxt; tag_prev = tag_cur; tag_cur = tag_nxt;
    }

    // finalize: common per-matrix power-of-2 scale across the 7 columns
    float q0, q1, q2, q3, q4, q5, q6, q7;
    upk2(q0, q1, P[0]); upk2(q2, q3, P[1]);
    upk2(q4, q5, P[2]); upk2(q6, q7, P[3]);
    float pm = fmaxf(fmaxf(fmaxf(q0, q1), fmaxf(q2, q3)),
                     fmaxf(fmaxf(q4, q5), q6));
    int te = (c < 7) ? (m + fexp(pm)) : -1000000000;
    te = max(te, __shfl_xor_sync(0xffffffffu, te, 4, 8));
    te = max(te, __shfl_xor_sync(0xffffffffu, te, 2, 8));
    te = max(te, __shfl_xor_sync(0xffffffffu, te, 1, 8));
    float sc = p2f(m - te);

    float* out = g_M + ((size_t)b * CH + k) * 64;
    if (c < 7) {
        out[0 * 8 + c] = q0 * sc;  out[1 * 8 + c] = q1 * sc;
        out[2 * 8 + c] = q2 * sc;  out[3 * 8 + c] = q3 * sc;
        out[4 * 8 + c] = q4 * sc;  out[5 * 8 + c] = q5 * sc;
        out[6 * 8 + c] = q6 * sc;
    }
    if (c == 0) g_Msc[b * CH + k]  = te;
    if (c == 7) g_goldP[b * CH + k] = gacc;
}

// 4 sequences per warp; lanes 0..6 of each 8-lane group own rows.
__global__ __launch_bounds__(128) void combine_kernel(
    const float* __restrict__ feats, const float* __restrict__ trans,
    const int* __restrict__ tags, const int* __restrict__ lengths)
{
    int w    = (blockIdx.x * 128 + threadIdx.x) >> 5;
    int lane = threadIdx.x & 31;
    int g = lane >> 3, j = lane & 7;
    int b = w * 4 + g;
    bool act = (j < 7);
    const unsigned FM = 0xffffffffu;

    float f0 = act ? feats[(size_t)b * TT * KK + j] : 0.0f;
    float vl = act ? (trans[j * KK + 7] + f0) : -1e30f;
    float vmax = vl;
    vmax = fmaxf(vmax, __shfl_xor_sync(FM, vmax, 4, 8));
    vmax = fmaxf(vmax, __shfl_xor_sync(FM, vmax, 2, 8));
    vmax = fmaxf(vmax, __shfl_xor_sync(FM, vmax, 1, 8));
    float v = act ? __expf(vl - vmax) : 0.0f;

    int len = lengths[b];
    int tag0 = tags[(size_t)b * TT];
    float ftag0 = __shfl_sync(FM, f0, tag0, 8);
    float gold = trans[tag0 * KK + 7] + ftag0
               + trans[8 * KK + tags[(size_t)b * TT + len - 1]];

    const float* gp = g_goldP + (size_t)b * CH;
    float gs = 0.0f;
#pragma unroll
    for (int i = 0; i < 8; i++) gs += gp[j + 8 * i];
    gs += __shfl_xor_sync(FM, gs, 4, 8);
    gs += __shfl_xor_sync(FM, gs, 2, 8);
    gs += __shfl_xor_sync(FM, gs, 1, 8);
    gold += gs;

    const float4* rp = (const float4*)(g_M + (size_t)b * CH * 64 + j * 8);
    const int* Sb = g_Msc + b * CH;
    int msum = 0, macc = 0;

    float4 a0 = rp[0],  a1 = rp[1];        // matrix k   (16 float4 stride)
    float4 b0 = rp[16], b1 = rp[17];       // matrix k+1

    for (int kk = 0; kk < CH; kk += 2) {
        float4 n0 = {0,0,0,0}, n1 = {0,0,0,0}, n2 = {0,0,0,0}, n3 = {0,0,0,0};
        if (kk + 2 < CH) { n0 = rp[(kk + 2) * 16]; n1 = rp[(kk + 2) * 16 + 1]; }
        msum += Sb[kk] + Sb[kk + 1];

        float vv0 = __shfl_sync(FM, v, 0, 8), vv1 = __shfl_sync(FM, v, 1, 8);
        float vv2 = __shfl_sync(FM, v, 2, 8), vv3 = __shfl_sync(FM, v, 3, 8);
        float vv4 = __shfl_sync(FM, v, 4, 8), vv5 = __shfl_sync(FM, v, 5, 8);
        float vv6 = __shfl_sync(FM, v, 6, 8);
        if (act) {
            float a = a0.x * vv0;
            a = fmaf(a0.y, vv1, a); a = fmaf(a0.z, vv2, a);
            a = fmaf(a0.w, vv3, a); a = fmaf(a1.x, vv4, a);
            a = fmaf(a1.y, vv5, a); a = fmaf(a1.z, vv6, a);
            v = a;
        }
        if (kk + 3 < CH) { n2 = rp[(kk + 3) * 16]; n3 = rp[(kk + 3) * 16 + 1]; }

        vv0 = __shfl_sync(FM, v, 0, 8); vv1 = __shfl_sync(FM, v, 1, 8);
        vv2 = __shfl_sync(FM, v, 2, 8); vv3 = __shfl_sync(FM, v, 3, 8);
        vv4 = __shfl_sync(FM, v, 4, 8); vv5 = __shfl_sync(FM, v, 5, 8);
        vv6 = __shfl_sync(FM, v, 6, 8);
        if (act) {
            float a = b0.x * vv0;
            a = fmaf(b0.y, vv1, a); a = fmaf(b0.z, vv2, a);
            a = fmaf(b0.w, vv3, a); a = fmaf(b1.x, vv4, a);
            a = fmaf(b1.y, vv5, a); a = fmaf(b1.z, vv6, a);
            v = a;
        }

        if ((kk & 3) == 2) {   // after folds where (fold index & 3) == 3
            float mx = v;
            mx = fmaxf(mx, __shfl_xor_sync(FM, mx, 4, 8));
            mx = fmaxf(mx, __shfl_xor_sync(FM, mx, 2, 8));
            mx = fmaxf(mx, __shfl_xor_sync(FM, mx, 1, 8));
            int e = fexp(mx);
            v *= p2f(-e);
            macc += e;
        }
        a0 = n0; a1 = n1; b0 = n2; b1 = n3;
    }

    float Est = act ? __expf(trans[8 * KK + j]) : 0.0f;
    float d = v * Est;
    d += __shfl_xor_sync(FM, d, 4, 8);
    d += __shfl_xor_sync(FM, d, 2, 8);
    d += __shfl_xor_sync(FM, d, 1, 8);
    float fwd = vmax + (float)(msum + macc) * LN2 + __logf(d);
    if (j == 0) g_diff[b] = fwd - gold;
}

__global__ void final_kernel(float* __restrict__ out)
{
    __shared__ float sm[256];
    float a = 0.0f;
    for (int i = threadIdx.x; i < BB; i += 256)
        a += g_diff[i];
    sm[threadIdx.x] = a;
    __syncthreads();
    for (int o = 128; o > 0; o >>= 1) {
        if (threadIdx.x < o) sm[threadIdx.x] += sm[threadIdx.x + o];
        __syncthreads();
    }
    if (threadIdx.x == 0) out[0] = sm[0] / (float)BB;
}

extern "C" void kernel_launch(void* const* d_in, const int* in_sizes, int n_in,
                              void* d_out, int out_size)
{
    const float* feats   = (const float*)d_in[0];
    const float* trans   = (const float*)d_in[1];
    const int*   tags    = (const int*)d_in[2];
    const int*   lengths = (const int*)d_in[3];
    float* out = (float*)d_out;

    prep_kernel<<<1, 64>>>(trans);
    chunk_kernel<<<(BB * 16 * 32) / 128, 128>>>(feats, trans, tags, lengths);
    combine_kernel<<<(BB / 4 * 32) / 128, 128>>>(feats, trans, tags, lengths);
    final_kernel<<<1, 256>>>(out);
}